// round 2
// baseline (speedup 1.0000x reference)
#include <cuda_runtime.h>
#include <math.h>

// Problem constants (fixed by the reference): B=4, S=2048, H=2048, I=4096, E=8, K=2
#define T_TOK 8192
#define H_DIM 2048
#define I_DIM 4096
#define N_EXP 8
#define K_TOP 2
#define TK (T_TOK * K_TOP)

// ---------------- device scratch (no dynamic allocation allowed) ----------------
__device__ int   g_counts[N_EXP];
__device__ int   g_seg[N_EXP + 1];
__device__ int   g_cursor[N_EXP];
__device__ int   g_expidx[TK];
__device__ float g_expw[TK];
__device__ int   g_rowtok[TK];   // sorted row -> source token
__device__ float g_roww[TK];     // sorted row -> routing weight
__device__ float g_h[(size_t)TK * I_DIM];  // intermediate activations (256 MB)

// ---------------- helpers ----------------
__device__ __forceinline__ float gelu_tanh(float v) {
    const float c = 0.7978845608028654f;  // sqrt(2/pi)
    float u = c * (v + 0.044715f * v * v * v);
    return 0.5f * v * (1.0f + tanhf(u));
}

// ---------------- kernels ----------------
__global__ void init_kernel() {
    if (threadIdx.x < N_EXP) g_counts[threadIdx.x] = 0;
}

// One warp per token: logits (E=8 dots of length H), softmax, top-2, histogram.
__global__ void router_kernel(const float* __restrict__ x,
                              const float* __restrict__ rw) {
    int warp = (blockIdx.x * blockDim.x + threadIdx.x) >> 5;
    int lane = threadIdx.x & 31;
    if (warp >= T_TOK) return;

    const float* xr = x + (size_t)warp * H_DIM;
    float acc[N_EXP];
#pragma unroll
    for (int e = 0; e < N_EXP; e++) acc[e] = 0.0f;

    for (int h = lane; h < H_DIM; h += 32) {
        float xv = xr[h];
#pragma unroll
        for (int e = 0; e < N_EXP; e++)
            acc[e] = fmaf(xv, rw[e * H_DIM + h], acc[e]);
    }
#pragma unroll
    for (int off = 16; off > 0; off >>= 1) {
#pragma unroll
        for (int e = 0; e < N_EXP; e++)
            acc[e] += __shfl_xor_sync(0xffffffffu, acc[e], off);
    }

    if (lane == 0) {
        float mx = acc[0];
#pragma unroll
        for (int e = 1; e < N_EXP; e++) mx = fmaxf(mx, acc[e]);
        float p[N_EXP];
        float s = 0.0f;
#pragma unroll
        for (int e = 0; e < N_EXP; e++) { p[e] = expf(acc[e] - mx); s += p[e]; }
        float inv = 1.0f / s;

        // top-2 (strict > keeps lowest index on ties, matching lax.top_k)
        int e0 = 0;
#pragma unroll
        for (int e = 1; e < N_EXP; e++) if (p[e] > p[e0]) e0 = e;
        int e1 = (e0 == 0) ? 1 : 0;
#pragma unroll
        for (int e = 0; e < N_EXP; e++)
            if (e != e0 && p[e] > p[e1]) e1 = e;

        g_expidx[2 * warp + 0] = e0;
        g_expw [2 * warp + 0] = p[e0] * inv;
        g_expidx[2 * warp + 1] = e1;
        g_expw [2 * warp + 1] = p[e1] * inv;
        atomicAdd(&g_counts[e0], 1);
        atomicAdd(&g_counts[e1], 1);
    }
}

// Tiny serial exclusive scan over 8 experts; also emits tokens_per_expert tail.
__global__ void scan_kernel(float* tpe_out, int write_tpe) {
    if (blockIdx.x == 0 && threadIdx.x == 0) {
        int s = 0;
        for (int e = 0; e < N_EXP; e++) {
            g_seg[e] = s;
            g_cursor[e] = s;
            int c = g_counts[e];
            if (write_tpe) tpe_out[e] = (float)c;
            s += c;
        }
        g_seg[N_EXP] = s;
    }
}

// Bucket (counting-sort) scatter of dispatched rows into expert-sorted order.
__global__ void scatter_kernel() {
    int i = blockIdx.x * blockDim.x + threadIdx.x;
    if (i >= TK) return;
    int e = g_expidx[i];
    int p = atomicAdd(&g_cursor[e], 1);
    g_rowtok[p] = i >> 1;        // source token (order // K)
    g_roww[p]   = g_expw[i];
}

// ---------------- grouped GEMM 1: h = gelu( gather(x) @ w1[e] ) ----------------
// Tiles: BM=128 BN=128 BK=8, 256 threads, 8x8 per-thread micro-tile.
__global__ __launch_bounds__(256, 2)
void gemm1_kernel(const float* __restrict__ x, const float* __restrict__ w1) {
    const int BM = 128, BN = 128, BK = 8;
    int e = blockIdx.z;
    int seg0 = g_seg[e];
    int seg1 = g_seg[e + 1];
    int row0 = seg0 + blockIdx.y * BM;
    if (row0 >= seg1) return;
    int n0 = blockIdx.x * BN;

    __shared__ float As[BK][BM];
    __shared__ float Bs[BK][BN];

    const float* Bp = w1 + (size_t)e * H_DIM * I_DIM;  // [H][I], n contiguous

    int tid  = threadIdx.x;
    int arow = tid >> 1;              // 0..127
    int ak   = (tid & 1) << 2;        // 0 or 4
    int grow = row0 + arow;
    bool avalid = (grow < seg1);
    const float* aptr = x;            // dummy
    if (avalid) {
        int tok = g_rowtok[grow];
        aptr = x + (size_t)tok * H_DIM + ak;
    }
    int bk = tid >> 5;                // 0..7
    int bn = (tid & 31) << 2;         // 0..124
    const float* bptr = Bp + (size_t)bk * I_DIM + n0 + bn;

    int ty = tid >> 4, tx = tid & 15;
    float acc[8][8];
#pragma unroll
    for (int i = 0; i < 8; i++)
#pragma unroll
        for (int j = 0; j < 8; j++) acc[i][j] = 0.0f;

    for (int k0 = 0; k0 < H_DIM; k0 += BK) {
        float4 av = make_float4(0.f, 0.f, 0.f, 0.f);
        if (avalid) av = *reinterpret_cast<const float4*>(aptr + k0);
        float4 bv = *reinterpret_cast<const float4*>(bptr + (size_t)k0 * I_DIM);

        __syncthreads();
        As[ak + 0][arow] = av.x;
        As[ak + 1][arow] = av.y;
        As[ak + 2][arow] = av.z;
        As[ak + 3][arow] = av.w;
        *reinterpret_cast<float4*>(&Bs[bk][bn]) = bv;
        __syncthreads();

#pragma unroll
        for (int kk = 0; kk < BK; kk++) {
            float4 a0 = *reinterpret_cast<const float4*>(&As[kk][ty * 8]);
            float4 a1 = *reinterpret_cast<const float4*>(&As[kk][ty * 8 + 4]);
            float4 b0 = *reinterpret_cast<const float4*>(&Bs[kk][tx * 8]);
            float4 b1 = *reinterpret_cast<const float4*>(&Bs[kk][tx * 8 + 4]);
            float af[8] = {a0.x, a0.y, a0.z, a0.w, a1.x, a1.y, a1.z, a1.w};
            float bf[8] = {b0.x, b0.y, b0.z, b0.w, b1.x, b1.y, b1.z, b1.w};
#pragma unroll
            for (int i = 0; i < 8; i++)
#pragma unroll
                for (int j = 0; j < 8; j++)
                    acc[i][j] = fmaf(af[i], bf[j], acc[i][j]);
        }
    }

    // epilogue: GELU + store to g_h
#pragma unroll
    for (int i = 0; i < 8; i++) {
        int r = row0 + ty * 8 + i;
        if (r < seg1) {
            float* hp = g_h + (size_t)r * I_DIM + n0 + tx * 8;
            float4 v0 = make_float4(gelu_tanh(acc[i][0]), gelu_tanh(acc[i][1]),
                                    gelu_tanh(acc[i][2]), gelu_tanh(acc[i][3]));
            float4 v1 = make_float4(gelu_tanh(acc[i][4]), gelu_tanh(acc[i][5]),
                                    gelu_tanh(acc[i][6]), gelu_tanh(acc[i][7]));
            *reinterpret_cast<float4*>(hp)     = v0;
            *reinterpret_cast<float4*>(hp + 4) = v1;
        }
    }
}

// -------- grouped GEMM 2: y[tok] += (h @ w2[e]) * w  (weighted scatter-add) --------
__global__ __launch_bounds__(256, 2)
void gemm2_kernel(const float* __restrict__ w2, float* __restrict__ y) {
    const int BM = 128, BN = 128, BK = 8;
    int e = blockIdx.z;
    int seg0 = g_seg[e];
    int seg1 = g_seg[e + 1];
    int row0 = seg0 + blockIdx.y * BM;
    if (row0 >= seg1) return;
    int n0 = blockIdx.x * BN;

    __shared__ float As[BK][BM];
    __shared__ float Bs[BK][BN];

    const float* Bp = w2 + (size_t)e * I_DIM * H_DIM;  // [I][H], n contiguous

    int tid  = threadIdx.x;
    int arow = tid >> 1;
    int ak   = (tid & 1) << 2;
    int grow = row0 + arow;
    bool avalid = (grow < seg1);
    const float* aptr = g_h;
    if (avalid) aptr = g_h + (size_t)grow * I_DIM + ak;

    int bk = tid >> 5;
    int bn = (tid & 31) << 2;
    const float* bptr = Bp + (size_t)bk * H_DIM + n0 + bn;

    int ty = tid >> 4, tx = tid & 15;
    float acc[8][8];
#pragma unroll
    for (int i = 0; i < 8; i++)
#pragma unroll
        for (int j = 0; j < 8; j++) acc[i][j] = 0.0f;

    for (int k0 = 0; k0 < I_DIM; k0 += BK) {
        float4 av = make_float4(0.f, 0.f, 0.f, 0.f);
        if (avalid) av = *reinterpret_cast<const float4*>(aptr + k0);
        float4 bv = *reinterpret_cast<const float4*>(bptr + (size_t)k0 * H_DIM);

        __syncthreads();
        As[ak + 0][arow] = av.x;
        As[ak + 1][arow] = av.y;
        As[ak + 2][arow] = av.z;
        As[ak + 3][arow] = av.w;
        *reinterpret_cast<float4*>(&Bs[bk][bn]) = bv;
        __syncthreads();

#pragma unroll
        for (int kk = 0; kk < BK; kk++) {
            float4 a0 = *reinterpret_cast<const float4*>(&As[kk][ty * 8]);
            float4 a1 = *reinterpret_cast<const float4*>(&As[kk][ty * 8 + 4]);
            float4 b0 = *reinterpret_cast<const float4*>(&Bs[kk][tx * 8]);
            float4 b1 = *reinterpret_cast<const float4*>(&Bs[kk][tx * 8 + 4]);
            float af[8] = {a0.x, a0.y, a0.z, a0.w, a1.x, a1.y, a1.z, a1.w};
            float bf[8] = {b0.x, b0.y, b0.z, b0.w, b1.x, b1.y, b1.z, b1.w};
#pragma unroll
            for (int i = 0; i < 8; i++)
#pragma unroll
                for (int j = 0; j < 8; j++)
                    acc[i][j] = fmaf(af[i], bf[j], acc[i][j]);
        }
    }

    // epilogue: weighted scatter-add into y (exactly 2 contributions per token,
    // fp add onto 0 is commutative -> deterministic)
#pragma unroll
    for (int i = 0; i < 8; i++) {
        int r = row0 + ty * 8 + i;
        if (r < seg1) {
            int tok  = g_rowtok[r];
            float wr = g_roww[r];
            float* yp = y + (size_t)tok * H_DIM + n0 + tx * 8;
#pragma unroll
            for (int j = 0; j < 8; j++)
                atomicAdd(&yp[j], acc[i][j] * wr);
        }
    }
}

// ---------------- launch ----------------
extern "C" void kernel_launch(void* const* d_in, const int* in_sizes, int n_in,
                              void* d_out, int out_size) {
    const float* x  = (const float*)d_in[0];   // [B,S,H] fp32
    const float* rw = (const float*)d_in[1];   // [E,H]
    const float* w1 = (const float*)d_in[2];   // [E,H,I]
    const float* w2 = (const float*)d_in[3];   // [E,I,H]
    float* y = (float*)d_out;

    // zero y (d_out is poisoned); tokens_per_expert tail written by scan_kernel
    cudaMemsetAsync(d_out, 0, (size_t)T_TOK * H_DIM * sizeof(float));

    init_kernel<<<1, 32>>>();
    router_kernel<<<T_TOK / 8, 256>>>(x, rw);   // 8 warps/block -> 8 tokens/block

    int write_tpe = (out_size >= T_TOK * H_DIM + N_EXP) ? 1 : 0;
    scan_kernel<<<1, 1>>>(y + (size_t)T_TOK * H_DIM, write_tpe);
    scatter_kernel<<<TK / 256, 256>>>();

    dim3 g1(I_DIM / 128, (TK + 127) / 128, N_EXP);
    gemm1_kernel<<<g1, 256>>>(x, w1);

    dim3 g2(H_DIM / 128, (TK + 127) / 128, N_EXP);
    gemm2_kernel<<<g2, 256>>>(w2, y);
}

// round 6
// speedup vs baseline: 2.1351x; 2.1351x over previous
#include <cuda_runtime.h>
#include <cuda_bf16.h>
#include <math.h>
#include <stdint.h>

// Problem constants: B=4, S=2048, H=2048, I=4096, E=8, K=2
#define T_TOK 8192
#define H_DIM 2048
#define I_DIM 4096
#define N_EXP 8
#define K_TOP 2
#define TK (T_TOK * K_TOP)
#define TKB (TK + 256)   // pad for +127 tile overread

// ---------------- device scratch (R1-proven set) ----------------
__device__ int   g_counts[N_EXP];
__device__ int   g_seg[N_EXP + 1];
__device__ int   g_cursor[N_EXP];
__device__ int   g_expidx[TK];
__device__ float g_expw[TK];
__device__ int   g_rowtok[TKB];
__device__ float g_roww[TKB];
__device__ float g_h[(size_t)TK * I_DIM];   // intermediate activations (fp32, 256MB)

// ---------------- helpers ----------------
__device__ __forceinline__ float gelu_tanh(float v) {
    const float c = 0.7978845608028654f;
    float u = c * (v + 0.044715f * v * v * v);
    return 0.5f * v * (1.0f + tanhf(u));
}
__device__ __forceinline__ void mma16816(float* c, uint32_t a0, uint32_t a1,
                                         uint32_t a2, uint32_t a3,
                                         uint32_t b0, uint32_t b1) {
    asm volatile(
        "mma.sync.aligned.m16n8k16.row.col.f32.bf16.bf16.f32 "
        "{%0,%1,%2,%3}, {%4,%5,%6,%7}, {%8,%9}, {%0,%1,%2,%3};"
        : "+f"(c[0]), "+f"(c[1]), "+f"(c[2]), "+f"(c[3])
        : "r"(a0), "r"(a1), "r"(a2), "r"(a3), "r"(b0), "r"(b1));
}
// split two fp32 (f.x = element k, f.y = element k+1) into hi/lo bf16x2 regs.
// b32 low half = first (lower-k) element, as required by mma fragments.
__device__ __forceinline__ void cvt_pair(float2 f, uint32_t& hi, uint32_t& lo) {
    asm("cvt.rn.bf16x2.f32 %0, %1, %2;" : "=r"(hi) : "f"(f.y), "f"(f.x));
    float f0h = __uint_as_float(hi << 16);
    float f1h = __uint_as_float(hi & 0xffff0000u);
    float r0 = f.x - f0h;
    float r1 = f.y - f1h;
    asm("cvt.rn.bf16x2.f32 %0, %1, %2;" : "=r"(lo) : "f"(r1), "f"(r0));
}

// ---------------- small kernels (verbatim from passing R1) ----------------
__global__ void init_kernel() {
    if (threadIdx.x < N_EXP) g_counts[threadIdx.x] = 0;
}

__global__ void router_kernel(const float* __restrict__ x,
                              const float* __restrict__ rw) {
    int warp = (blockIdx.x * blockDim.x + threadIdx.x) >> 5;
    int lane = threadIdx.x & 31;
    if (warp >= T_TOK) return;
    const float* xr = x + (size_t)warp * H_DIM;
    float acc[N_EXP];
#pragma unroll
    for (int e = 0; e < N_EXP; e++) acc[e] = 0.0f;
    for (int h = lane; h < H_DIM; h += 32) {
        float xv = xr[h];
#pragma unroll
        for (int e = 0; e < N_EXP; e++)
            acc[e] = fmaf(xv, rw[e * H_DIM + h], acc[e]);
    }
#pragma unroll
    for (int off = 16; off > 0; off >>= 1)
#pragma unroll
        for (int e = 0; e < N_EXP; e++)
            acc[e] += __shfl_xor_sync(0xffffffffu, acc[e], off);
    if (lane == 0) {
        float mx = acc[0];
#pragma unroll
        for (int e = 1; e < N_EXP; e++) mx = fmaxf(mx, acc[e]);
        float p[N_EXP]; float s = 0.0f;
#pragma unroll
        for (int e = 0; e < N_EXP; e++) { p[e] = expf(acc[e] - mx); s += p[e]; }
        float inv = 1.0f / s;
        int e0 = 0;
#pragma unroll
        for (int e = 1; e < N_EXP; e++) if (p[e] > p[e0]) e0 = e;
        int e1 = (e0 == 0) ? 1 : 0;
#pragma unroll
        for (int e = 0; e < N_EXP; e++) if (e != e0 && p[e] > p[e1]) e1 = e;
        g_expidx[2 * warp + 0] = e0; g_expw[2 * warp + 0] = p[e0] * inv;
        g_expidx[2 * warp + 1] = e1; g_expw[2 * warp + 1] = p[e1] * inv;
        atomicAdd(&g_counts[e0], 1);
        atomicAdd(&g_counts[e1], 1);
    }
}

__global__ void scan_kernel(float* tpe_out, int write_tpe) {
    if (blockIdx.x == 0 && threadIdx.x == 0) {
        int s = 0;
        for (int e = 0; e < N_EXP; e++) {
            g_seg[e] = s;
            g_cursor[e] = s;
            int c = g_counts[e];
            if (write_tpe) tpe_out[e] = (float)c;
            s += c;
        }
        g_seg[N_EXP] = s;
    }
}

__global__ void scatter_kernel() {
    int i = blockIdx.x * blockDim.x + threadIdx.x;
    if (i >= TK) return;
    int e = g_expidx[i];
    int p = atomicAdd(&g_cursor[e], 1);
    g_rowtok[p] = i >> 1;
    g_roww[p]   = g_expw[i];
}

// ---------------- mma.sync grouped GEMMs -----------------------------------
// CTA 128x128x16, 8 warps (2M x 4N), warp tile 64x32.
// fp32 smem tiles (double-buffered), bf16 hi/lo split computed on the fly.
#define PA 20    // A tile pitch in words (80B, 16B-aligned rows, conflict-light)
#define PB 132   // B tile pitch in words (528B)
#define BKK 16

__global__ __launch_bounds__(256, 2)
void gemm1_mma(const float* __restrict__ x, const float* __restrict__ w1) {
    __shared__ __align__(16) float As[2][128 * PA];
    __shared__ __align__(16) float Bs[2][BKK * PB];

    int e = blockIdx.z;
    int seg0 = g_seg[e], seg1 = g_seg[e + 1];
    int row0 = seg0 + blockIdx.y * 128;
    if (row0 >= seg1) return;
    int n0 = blockIdx.x * 128;

    const float* Bp = w1 + (size_t)e * H_DIM * I_DIM;   // [H][I]

    int tid = threadIdx.x;
    int wid = tid >> 5, l = tid & 31;
    int wm = wid >> 2, wn = wid & 3;
    int r7 = l >> 2, c2 = (l & 3) * 2;

    // A loader mapping: 512 float4 (128 rows x 4 quads), 2 per thread (gathered)
    int ia0 = tid, ia1 = tid + 256;
    int ar0 = ia0 >> 2, aq0 = ia0 & 3;
    int ar1 = ia1 >> 2, aq1 = ia1 & 3;
    int tok0 = g_rowtok[row0 + ar0];
    int tok1 = g_rowtok[row0 + ar1];
    const float4* asrc0 = (const float4*)(x + (size_t)tok0 * H_DIM) + aq0;
    const float4* asrc1 = (const float4*)(x + (size_t)tok1 * H_DIM) + aq1;
    // B loader mapping: 512 float4 (16 rows x 32 quads)
    int br0 = ia0 >> 5, bq0 = ia0 & 31;
    int br1 = ia1 >> 5, bq1 = ia1 & 31;
    const float4* bsrc0 = (const float4*)(Bp + (size_t)br0 * I_DIM + n0) + bq0;
    const float4* bsrc1 = (const float4*)(Bp + (size_t)br1 * I_DIM + n0) + bq1;
    const size_t bstep = (size_t)4 * I_DIM;   // 16 rows in float4 units

    float acc[4][4][4];
#pragma unroll
    for (int mi = 0; mi < 4; mi++)
#pragma unroll
        for (int ni = 0; ni < 4; ni++)
#pragma unroll
            for (int q = 0; q < 4; q++) acc[mi][ni][q] = 0.0f;

    const int NC = H_DIM / BKK;   // 128
    float4 av0 = asrc0[0], av1 = asrc1[0];
    float4 bv0 = bsrc0[0], bv1 = bsrc1[0];

    for (int c = 0; c < NC; c++) {
        int s = c & 1;
        *(float4*)&As[s][ar0 * PA + aq0 * 4] = av0;
        *(float4*)&As[s][ar1 * PA + aq1 * 4] = av1;
        *(float4*)&Bs[s][br0 * PB + bq0 * 4] = bv0;
        *(float4*)&Bs[s][br1 * PB + bq1 * 4] = bv1;
        if (c + 1 < NC) {
            int k4 = (c + 1) * (BKK / 4);
            av0 = asrc0[k4];                 av1 = asrc1[k4];
            bv0 = bsrc0[(size_t)(c + 1) * bstep];
            bv1 = bsrc1[(size_t)(c + 1) * bstep];
        }
        __syncthreads();

        const float* as = As[s];
        const float* bs = Bs[s];
        uint32_t aH[4][4], aL[4][4];
#pragma unroll
        for (int mi = 0; mi < 4; mi++) {
            int m = wm * 64 + mi * 16 + r7;
#pragma unroll
            for (int p = 0; p < 4; p++) {
                int rr = m + (p & 1) * 8;
                int kk = c2 + (p >> 1) * 8;
                float2 f = *(const float2*)&as[rr * PA + kk];
                cvt_pair(f, aH[mi][p], aL[mi][p]);
            }
        }
#pragma unroll
        for (int ni = 0; ni < 4; ni++) {
            int n = wn * 32 + ni * 8 + r7;
            float2 fb0 = make_float2(bs[c2 * PB + n], bs[(c2 + 1) * PB + n]);
            float2 fb1 = make_float2(bs[(c2 + 8) * PB + n], bs[(c2 + 9) * PB + n]);
            uint32_t bh0, bl0, bh1, bl1;
            cvt_pair(fb0, bh0, bl0);
            cvt_pair(fb1, bh1, bl1);
#pragma unroll
            for (int mi = 0; mi < 4; mi++) {
                mma16816(acc[mi][ni], aH[mi][0], aH[mi][1], aH[mi][2], aH[mi][3], bh0, bh1);
                mma16816(acc[mi][ni], aH[mi][0], aH[mi][1], aH[mi][2], aH[mi][3], bl0, bl1);
                mma16816(acc[mi][ni], aL[mi][0], aL[mi][1], aL[mi][2], aL[mi][3], bh0, bh1);
            }
        }
    }

    // epilogue: GELU -> g_h (fp32), valid rows only
#pragma unroll
    for (int mi = 0; mi < 4; mi++) {
        int r1 = row0 + wm * 64 + mi * 16 + r7;
        int r2 = r1 + 8;
#pragma unroll
        for (int ni = 0; ni < 4; ni++) {
            int col = n0 + wn * 32 + ni * 8 + c2;
            if (r1 < seg1) {
                float2 v = make_float2(gelu_tanh(acc[mi][ni][0]), gelu_tanh(acc[mi][ni][1]));
                *(float2*)&g_h[(size_t)r1 * I_DIM + col] = v;
            }
            if (r2 < seg1) {
                float2 v = make_float2(gelu_tanh(acc[mi][ni][2]), gelu_tanh(acc[mi][ni][3]));
                *(float2*)&g_h[(size_t)r2 * I_DIM + col] = v;
            }
        }
    }
}

__global__ __launch_bounds__(256, 2)
void gemm2_mma(const float* __restrict__ w2, float* __restrict__ y) {
    __shared__ __align__(16) float As[2][128 * PA];
    __shared__ __align__(16) float Bs[2][BKK * PB];

    int e = blockIdx.z;
    int seg0 = g_seg[e], seg1 = g_seg[e + 1];
    int row0 = seg0 + blockIdx.y * 128;
    if (row0 >= seg1) return;
    int n0 = blockIdx.x * 128;

    const float* Bp = w2 + (size_t)e * I_DIM * H_DIM;   // [I][H]

    int tid = threadIdx.x;
    int wid = tid >> 5, l = tid & 31;
    int wm = wid >> 2, wn = wid & 3;
    int r7 = l >> 2, c2 = (l & 3) * 2;

    int ia0 = tid, ia1 = tid + 256;
    int ar0 = ia0 >> 2, aq0 = ia0 & 3;
    int ar1 = ia1 >> 2, aq1 = ia1 & 3;
    const float4* asrc0 = (const float4*)(g_h + (size_t)(row0 + ar0) * I_DIM) + aq0;
    const float4* asrc1 = (const float4*)(g_h + (size_t)(row0 + ar1) * I_DIM) + aq1;
    int br0 = ia0 >> 5, bq0 = ia0 & 31;
    int br1 = ia1 >> 5, bq1 = ia1 & 31;
    const float4* bsrc0 = (const float4*)(Bp + (size_t)br0 * H_DIM + n0) + bq0;
    const float4* bsrc1 = (const float4*)(Bp + (size_t)br1 * H_DIM + n0) + bq1;
    const size_t bstep = (size_t)4 * H_DIM;

    float acc[4][4][4];
#pragma unroll
    for (int mi = 0; mi < 4; mi++)
#pragma unroll
        for (int ni = 0; ni < 4; ni++)
#pragma unroll
            for (int q = 0; q < 4; q++) acc[mi][ni][q] = 0.0f;

    const int NC = I_DIM / BKK;   // 256
    float4 av0 = asrc0[0], av1 = asrc1[0];
    float4 bv0 = bsrc0[0], bv1 = bsrc1[0];

    for (int c = 0; c < NC; c++) {
        int s = c & 1;
        *(float4*)&As[s][ar0 * PA + aq0 * 4] = av0;
        *(float4*)&As[s][ar1 * PA + aq1 * 4] = av1;
        *(float4*)&Bs[s][br0 * PB + bq0 * 4] = bv0;
        *(float4*)&Bs[s][br1 * PB + bq1 * 4] = bv1;
        if (c + 1 < NC) {
            int k4 = (c + 1) * (BKK / 4);
            av0 = asrc0[k4];                 av1 = asrc1[k4];
            bv0 = bsrc0[(size_t)(c + 1) * bstep];
            bv1 = bsrc1[(size_t)(c + 1) * bstep];
        }
        __syncthreads();

        const float* as = As[s];
        const float* bs = Bs[s];
        uint32_t aH[4][4], aL[4][4];
#pragma unroll
        for (int mi = 0; mi < 4; mi++) {
            int m = wm * 64 + mi * 16 + r7;
#pragma unroll
            for (int p = 0; p < 4; p++) {
                int rr = m + (p & 1) * 8;
                int kk = c2 + (p >> 1) * 8;
                float2 f = *(const float2*)&as[rr * PA + kk];
                cvt_pair(f, aH[mi][p], aL[mi][p]);
            }
        }
#pragma unroll
        for (int ni = 0; ni < 4; ni++) {
            int n = wn * 32 + ni * 8 + r7;
            float2 fb0 = make_float2(bs[c2 * PB + n], bs[(c2 + 1) * PB + n]);
            float2 fb1 = make_float2(bs[(c2 + 8) * PB + n], bs[(c2 + 9) * PB + n]);
            uint32_t bh0, bl0, bh1, bl1;
            cvt_pair(fb0, bh0, bl0);
            cvt_pair(fb1, bh1, bl1);
#pragma unroll
            for (int mi = 0; mi < 4; mi++) {
                mma16816(acc[mi][ni], aH[mi][0], aH[mi][1], aH[mi][2], aH[mi][3], bh0, bh1);
                mma16816(acc[mi][ni], aH[mi][0], aH[mi][1], aH[mi][2], aH[mi][3], bl0, bl1);
                mma16816(acc[mi][ni], aL[mi][0], aL[mi][1], aL[mi][2], aL[mi][3], bh0, bh1);
            }
        }
    }

    // epilogue: weighted scatter-add into y (2 contributions/token, deterministic)
#pragma unroll
    for (int mi = 0; mi < 4; mi++) {
        int rr1 = row0 + wm * 64 + mi * 16 + r7;
        int rr2 = rr1 + 8;
        bool v1 = rr1 < seg1, v2 = rr2 < seg1;
        int t1 = v1 ? g_rowtok[rr1] : 0;
        int t2 = v2 ? g_rowtok[rr2] : 0;
        float w1r = v1 ? g_roww[rr1] : 0.0f;
        float w2r = v2 ? g_roww[rr2] : 0.0f;
        float* y1 = y + (size_t)t1 * H_DIM;
        float* y2 = y + (size_t)t2 * H_DIM;
#pragma unroll
        for (int ni = 0; ni < 4; ni++) {
            int col = n0 + wn * 32 + ni * 8 + c2;
            if (v1) {
                atomicAdd(y1 + col,     acc[mi][ni][0] * w1r);
                atomicAdd(y1 + col + 1, acc[mi][ni][1] * w1r);
            }
            if (v2) {
                atomicAdd(y2 + col,     acc[mi][ni][2] * w2r);
                atomicAdd(y2 + col + 1, acc[mi][ni][3] * w2r);
            }
        }
    }
}

// ---------------- launch ----------------
extern "C" void kernel_launch(void* const* d_in, const int* in_sizes, int n_in,
                              void* d_out, int out_size) {
    const float* x  = (const float*)d_in[0];   // [B,S,H]
    const float* rw = (const float*)d_in[1];   // [E,H]
    const float* w1 = (const float*)d_in[2];   // [E,H,I]
    const float* w2 = (const float*)d_in[3];   // [E,I,H]
    float* y = (float*)d_out;

    cudaMemsetAsync(d_out, 0, (size_t)T_TOK * H_DIM * sizeof(float));

    init_kernel<<<1, 32>>>();
    router_kernel<<<T_TOK / 8, 256>>>(x, rw);
    int write_tpe = (out_size >= T_TOK * H_DIM + N_EXP) ? 1 : 0;
    scan_kernel<<<1, 1>>>(y + (size_t)T_TOK * H_DIM, write_tpe);
    scatter_kernel<<<TK / 256, 256>>>();

    dim3 g1(I_DIM / 128, (TK + 127) / 128, N_EXP);
    gemm1_mma<<<g1, 256>>>(x, w1);

    dim3 g2(H_DIM / 128, (TK + 127) / 128, N_EXP);
    gemm2_mma<<<g2, 256>>>(w2, y);
}

// round 8
// speedup vs baseline: 2.7415x; 1.2840x over previous
#include <cuda_runtime.h>
#include <cuda_bf16.h>
#include <math.h>
#include <stdint.h>

// Problem constants: B=4, S=2048, H=2048, I=4096, E=8, K=2
#define T_TOK 8192
#define H_DIM 2048
#define I_DIM 4096
#define N_EXP 8
#define K_TOP 2
#define TK (T_TOK * K_TOP)
#define TKB (TK + 256)   // pad for +127 tile overread

// ---------------- device scratch ----------------
__device__ int   g_counts[N_EXP];
__device__ int   g_seg[N_EXP + 1];
__device__ int   g_cursor[N_EXP];
__device__ int   g_expidx[TK];
__device__ float g_expw[TK];
__device__ int   g_rowtok[TKB];
__device__ float g_roww[TKB];
__device__ __nv_bfloat16 g_h_hi[(size_t)TK * I_DIM];  // 128MB
__device__ __nv_bfloat16 g_h_lo[(size_t)TK * I_DIM];  // 128MB

// ---------------- helpers ----------------
__device__ __forceinline__ float gelu_tanh(float v) {
    const float c = 0.7978845608028654f;
    float u = c * (v + 0.044715f * v * v * v);
    return 0.5f * v * (1.0f + tanhf(u));
}
__device__ __forceinline__ void mma16816(float* c, uint32_t a0, uint32_t a1,
                                         uint32_t a2, uint32_t a3,
                                         uint32_t b0, uint32_t b1) {
    asm volatile(
        "mma.sync.aligned.m16n8k16.row.col.f32.bf16.bf16.f32 "
        "{%0,%1,%2,%3}, {%4,%5,%6,%7}, {%8,%9}, {%0,%1,%2,%3};"
        : "+f"(c[0]), "+f"(c[1]), "+f"(c[2]), "+f"(c[3])
        : "r"(a0), "r"(a1), "r"(a2), "r"(a3), "r"(b0), "r"(b1));
}
// split two fp32 (f.x = element k, f.y = element k+1) into hi/lo bf16x2 regs.
__device__ __forceinline__ void cvt_pair(float2 f, uint32_t& hi, uint32_t& lo) {
    asm("cvt.rn.bf16x2.f32 %0, %1, %2;" : "=r"(hi) : "f"(f.y), "f"(f.x));
    float f0h = __uint_as_float(hi << 16);
    float f1h = __uint_as_float(hi & 0xffff0000u);
    float r0 = f.x - f0h;
    float r1 = f.y - f1h;
    asm("cvt.rn.bf16x2.f32 %0, %1, %2;" : "=r"(lo) : "f"(r1), "f"(r0));
}

// ---------------- small kernels ----------------
__global__ void init_kernel() {
    int i = blockIdx.x * blockDim.x + threadIdx.x;
    if (i < TKB) { g_rowtok[i] = 0; g_roww[i] = 0.0f; }
    if (i < N_EXP) g_counts[i] = 0;
}

__global__ void router_kernel(const float* __restrict__ x,
                              const float* __restrict__ rw) {
    int warp = (blockIdx.x * blockDim.x + threadIdx.x) >> 5;
    int lane = threadIdx.x & 31;
    if (warp >= T_TOK) return;
    const float* xr = x + (size_t)warp * H_DIM;
    float acc[N_EXP];
#pragma unroll
    for (int e = 0; e < N_EXP; e++) acc[e] = 0.0f;
    for (int h = lane; h < H_DIM; h += 32) {
        float xv = xr[h];
#pragma unroll
        for (int e = 0; e < N_EXP; e++)
            acc[e] = fmaf(xv, rw[e * H_DIM + h], acc[e]);
    }
#pragma unroll
    for (int off = 16; off > 0; off >>= 1)
#pragma unroll
        for (int e = 0; e < N_EXP; e++)
            acc[e] += __shfl_xor_sync(0xffffffffu, acc[e], off);
    if (lane == 0) {
        float mx = acc[0];
#pragma unroll
        for (int e = 1; e < N_EXP; e++) mx = fmaxf(mx, acc[e]);
        float p[N_EXP]; float s = 0.0f;
#pragma unroll
        for (int e = 0; e < N_EXP; e++) { p[e] = expf(acc[e] - mx); s += p[e]; }
        float inv = 1.0f / s;
        int e0 = 0;
#pragma unroll
        for (int e = 1; e < N_EXP; e++) if (p[e] > p[e0]) e0 = e;
        int e1 = (e0 == 0) ? 1 : 0;
#pragma unroll
        for (int e = 0; e < N_EXP; e++) if (e != e0 && p[e] > p[e1]) e1 = e;
        g_expidx[2 * warp + 0] = e0; g_expw[2 * warp + 0] = p[e0] * inv;
        g_expidx[2 * warp + 1] = e1; g_expw[2 * warp + 1] = p[e1] * inv;
        atomicAdd(&g_counts[e0], 1);
        atomicAdd(&g_counts[e1], 1);
    }
}

__global__ void scan_kernel(float* tpe_out, int write_tpe) {
    if (blockIdx.x == 0 && threadIdx.x == 0) {
        int s = 0;
        for (int e = 0; e < N_EXP; e++) {
            g_seg[e] = s;
            g_cursor[e] = s;
            int c = g_counts[e];
            if (write_tpe) tpe_out[e] = (float)c;
            s += c;
        }
        g_seg[N_EXP] = s;
    }
}

__global__ void scatter_kernel() {
    int i = blockIdx.x * blockDim.x + threadIdx.x;
    if (i >= TK) return;
    int e = g_expidx[i];
    int p = atomicAdd(&g_cursor[e], 1);
    g_rowtok[p] = i >> 1;
    g_roww[p]   = g_expw[i];
}

// ---------------- mma.sync grouped GEMMs -----------------------------------
// CTA 128x128x16, 8 warps (2M x 4N), warp tile 64x32.
// A: bf16 hi/lo smem tiles (pitch 12 words, conflict-free fragment reads).
// B: fp32 smem tile (pitch 132 words), bf16 split on the fly.
#define PAW 12   // A tile pitch in 32-bit words (8 used + 4 pad)
#define PB 132   // B tile pitch in words
#define BKK 16

__global__ __launch_bounds__(256, 2)
void gemm1_mma(const float* __restrict__ x, const float* __restrict__ w1) {
    __shared__ __align__(16) uint32_t AsH[2][128 * PAW];
    __shared__ __align__(16) uint32_t AsL[2][128 * PAW];
    __shared__ __align__(16) float    Bs[2][BKK * PB];

    int e = blockIdx.z;
    int seg0 = g_seg[e], seg1 = g_seg[e + 1];
    int row0 = seg0 + blockIdx.y * 128;
    if (row0 >= seg1) return;
    int n0 = blockIdx.x * 128;

    const float* Bp = w1 + (size_t)e * H_DIM * I_DIM;   // [H][I]

    int tid = threadIdx.x;
    int wid = tid >> 5, l = tid & 31;
    int wm = wid >> 2, wn = wid & 3;
    int r7 = l >> 2, c2 = (l & 3) * 2;

    // A loader: 512 float4 (128 rows x 4 quads), 2 per thread (gathered rows)
    int ia0 = tid, ia1 = tid + 256;
    int ar0 = ia0 >> 2, aq0 = ia0 & 3;
    int ar1 = ia1 >> 2, aq1 = ia1 & 3;
    // pad rows read token 0 (init zeroed the tail); clamp for safety anyway
    int tok0 = min(g_rowtok[row0 + ar0], T_TOK - 1);
    int tok1 = min(g_rowtok[row0 + ar1], T_TOK - 1);
    const float4* asrc0 = (const float4*)(x + (size_t)tok0 * H_DIM) + aq0;
    const float4* asrc1 = (const float4*)(x + (size_t)tok1 * H_DIM) + aq1;
    // B loader: 512 float4 (16 rows x 32 quads)
    int br0 = ia0 >> 5, bq0 = ia0 & 31;
    int br1 = ia1 >> 5, bq1 = ia1 & 31;
    const float4* bsrc0 = (const float4*)(Bp + (size_t)br0 * I_DIM + n0) + bq0;
    const float4* bsrc1 = (const float4*)(Bp + (size_t)br1 * I_DIM + n0) + bq1;
    const size_t bstep = (size_t)4 * I_DIM;

    float acc[4][4][4];
#pragma unroll
    for (int mi = 0; mi < 4; mi++)
#pragma unroll
        for (int ni = 0; ni < 4; ni++)
#pragma unroll
            for (int q = 0; q < 4; q++) acc[mi][ni][q] = 0.0f;

    const int NC = H_DIM / BKK;   // 128
    float4 av0 = asrc0[0], av1 = asrc1[0];
    float4 bv0 = bsrc0[0], bv1 = bsrc1[0];

    for (int c = 0; c < NC; c++) {
        int s = c & 1;
        // convert A at store time: float4 -> 2 hi words + 2 lo words
        {
            uint32_t h0, l0, h1, l1;
            cvt_pair(make_float2(av0.x, av0.y), h0, l0);
            cvt_pair(make_float2(av0.z, av0.w), h1, l1);
            *(uint2*)&AsH[s][ar0 * PAW + aq0 * 2] = make_uint2(h0, h1);
            *(uint2*)&AsL[s][ar0 * PAW + aq0 * 2] = make_uint2(l0, l1);
            cvt_pair(make_float2(av1.x, av1.y), h0, l0);
            cvt_pair(make_float2(av1.z, av1.w), h1, l1);
            *(uint2*)&AsH[s][ar1 * PAW + aq1 * 2] = make_uint2(h0, h1);
            *(uint2*)&AsL[s][ar1 * PAW + aq1 * 2] = make_uint2(l0, l1);
        }
        *(float4*)&Bs[s][br0 * PB + bq0 * 4] = bv0;
        *(float4*)&Bs[s][br1 * PB + bq1 * 4] = bv1;
        if (c + 1 < NC) {
            int k4 = (c + 1) * (BKK / 4);
            av0 = asrc0[k4];                 av1 = asrc1[k4];
            bv0 = bsrc0[(size_t)(c + 1) * bstep];
            bv1 = bsrc1[(size_t)(c + 1) * bstep];
        }
        __syncthreads();

        const uint32_t* ash = AsH[s];
        const uint32_t* asl = AsL[s];
        const float*    bs  = Bs[s];
        uint32_t aH[4][4], aL[4][4];
#pragma unroll
        for (int mi = 0; mi < 4; mi++) {
            int m = wm * 64 + mi * 16 + r7;
#pragma unroll
            for (int p = 0; p < 4; p++) {
                int rr = m + (p & 1) * 8;
                int w  = (l & 3) + (p >> 1) * 4;
                aH[mi][p] = ash[rr * PAW + w];
                aL[mi][p] = asl[rr * PAW + w];
            }
        }
#pragma unroll
        for (int ni = 0; ni < 4; ni++) {
            int n = wn * 32 + ni * 8 + r7;
            float2 fb0 = make_float2(bs[c2 * PB + n], bs[(c2 + 1) * PB + n]);
            float2 fb1 = make_float2(bs[(c2 + 8) * PB + n], bs[(c2 + 9) * PB + n]);
            uint32_t bh0, bl0, bh1, bl1;
            cvt_pair(fb0, bh0, bl0);
            cvt_pair(fb1, bh1, bl1);
#pragma unroll
            for (int mi = 0; mi < 4; mi++) {
                mma16816(acc[mi][ni], aH[mi][0], aH[mi][1], aH[mi][2], aH[mi][3], bh0, bh1);
                mma16816(acc[mi][ni], aH[mi][0], aH[mi][1], aH[mi][2], aH[mi][3], bl0, bl1);
                mma16816(acc[mi][ni], aL[mi][0], aL[mi][1], aL[mi][2], aL[mi][3], bh0, bh1);
            }
        }
    }

    // epilogue: GELU -> split -> g_h_hi / g_h_lo (valid rows only)
#pragma unroll
    for (int mi = 0; mi < 4; mi++) {
        int r1 = row0 + wm * 64 + mi * 16 + r7;
        int r2 = r1 + 8;
#pragma unroll
        for (int ni = 0; ni < 4; ni++) {
            int col = n0 + wn * 32 + ni * 8 + c2;
            if (r1 < seg1) {
                float2 v = make_float2(gelu_tanh(acc[mi][ni][0]), gelu_tanh(acc[mi][ni][1]));
                uint32_t hw, lw;
                cvt_pair(v, hw, lw);
                size_t o = (size_t)r1 * I_DIM + col;
                *(uint32_t*)&g_h_hi[o] = hw;
                *(uint32_t*)&g_h_lo[o] = lw;
            }
            if (r2 < seg1) {
                float2 v = make_float2(gelu_tanh(acc[mi][ni][2]), gelu_tanh(acc[mi][ni][3]));
                uint32_t hw, lw;
                cvt_pair(v, hw, lw);
                size_t o = (size_t)r2 * I_DIM + col;
                *(uint32_t*)&g_h_hi[o] = hw;
                *(uint32_t*)&g_h_lo[o] = lw;
            }
        }
    }
}

__global__ __launch_bounds__(256, 2)
void gemm2_mma(const float* __restrict__ w2, float* __restrict__ y) {
    __shared__ __align__(16) uint32_t AsH[2][128 * PAW];
    __shared__ __align__(16) uint32_t AsL[2][128 * PAW];
    __shared__ __align__(16) float    Bs[2][BKK * PB];

    int e = blockIdx.z;
    int seg0 = g_seg[e], seg1 = g_seg[e + 1];
    int row0 = seg0 + blockIdx.y * 128;
    if (row0 >= seg1) return;
    int n0 = blockIdx.x * 128;

    const float* Bp = w2 + (size_t)e * I_DIM * H_DIM;   // [I][H]

    int tid = threadIdx.x;
    int wid = tid >> 5, l = tid & 31;
    int wm = wid >> 2, wn = wid & 3;
    int r7 = l >> 2, c2 = (l & 3) * 2;

    // A loader: 128 rows x 2 halves of pre-split bf16; CLAMP row to stay in bounds
    // (rows beyond seg1 produce garbage accs that the masked epilogue discards)
    int arow = tid >> 1, ahalf = tid & 1;
    int arid = min(row0 + arow, TK - 1);
    const uint4* ahsrc = (const uint4*)(g_h_hi + (size_t)arid * I_DIM) + ahalf;
    const uint4* alsrc = (const uint4*)(g_h_lo + (size_t)arid * I_DIM) + ahalf;
    // B loader: 512 float4 (16 rows x 32 quads)
    int ia0 = tid, ia1 = tid + 256;
    int br0 = ia0 >> 5, bq0 = ia0 & 31;
    int br1 = ia1 >> 5, bq1 = ia1 & 31;
    const float4* bsrc0 = (const float4*)(Bp + (size_t)br0 * H_DIM + n0) + bq0;
    const float4* bsrc1 = (const float4*)(Bp + (size_t)br1 * H_DIM + n0) + bq1;
    const size_t bstep = (size_t)4 * H_DIM;

    float acc[4][4][4];
#pragma unroll
    for (int mi = 0; mi < 4; mi++)
#pragma unroll
        for (int ni = 0; ni < 4; ni++)
#pragma unroll
            for (int q = 0; q < 4; q++) acc[mi][ni][q] = 0.0f;

    const int NC = I_DIM / BKK;   // 256
    uint4 avh = ahsrc[0], avl = alsrc[0];
    float4 bv0 = bsrc0[0], bv1 = bsrc1[0];

    for (int c = 0; c < NC; c++) {
        int s = c & 1;
        *(uint4*)&AsH[s][arow * PAW + ahalf * 4] = avh;
        *(uint4*)&AsL[s][arow * PAW + ahalf * 4] = avl;
        *(float4*)&Bs[s][br0 * PB + bq0 * 4] = bv0;
        *(float4*)&Bs[s][br1 * PB + bq1 * 4] = bv1;
        if (c + 1 < NC) {
            int k2 = (c + 1) * 2;   // 16 elems = 2 uint4 per chunk
            avh = ahsrc[k2];
            avl = alsrc[k2];
            bv0 = bsrc0[(size_t)(c + 1) * bstep];
            bv1 = bsrc1[(size_t)(c + 1) * bstep];
        }
        __syncthreads();

        const uint32_t* ash = AsH[s];
        const uint32_t* asl = AsL[s];
        const float*    bs  = Bs[s];
        uint32_t aH[4][4], aL[4][4];
#pragma unroll
        for (int mi = 0; mi < 4; mi++) {
            int m = wm * 64 + mi * 16 + r7;
#pragma unroll
            for (int p = 0; p < 4; p++) {
                int rr = m + (p & 1) * 8;
                int w  = (l & 3) + (p >> 1) * 4;
                aH[mi][p] = ash[rr * PAW + w];
                aL[mi][p] = asl[rr * PAW + w];
            }
        }
#pragma unroll
        for (int ni = 0; ni < 4; ni++) {
            int n = wn * 32 + ni * 8 + r7;
            float2 fb0 = make_float2(bs[c2 * PB + n], bs[(c2 + 1) * PB + n]);
            float2 fb1 = make_float2(bs[(c2 + 8) * PB + n], bs[(c2 + 9) * PB + n]);
            uint32_t bh0, bl0, bh1, bl1;
            cvt_pair(fb0, bh0, bl0);
            cvt_pair(fb1, bh1, bl1);
#pragma unroll
            for (int mi = 0; mi < 4; mi++) {
                mma16816(acc[mi][ni], aH[mi][0], aH[mi][1], aH[mi][2], aH[mi][3], bh0, bh1);
                mma16816(acc[mi][ni], aH[mi][0], aH[mi][1], aH[mi][2], aH[mi][3], bl0, bl1);
                mma16816(acc[mi][ni], aL[mi][0], aL[mi][1], aL[mi][2], aL[mi][3], bh0, bh1);
            }
        }
    }

    // epilogue: weighted scatter-add into y (invalid rows masked -> no NaN leak)
#pragma unroll
    for (int mi = 0; mi < 4; mi++) {
        int rr1 = row0 + wm * 64 + mi * 16 + r7;
        int rr2 = rr1 + 8;
        bool v1 = rr1 < seg1, v2 = rr2 < seg1;
        int t1 = v1 ? g_rowtok[rr1] : 0;
        int t2 = v2 ? g_rowtok[rr2] : 0;
        float w1r = v1 ? g_roww[rr1] : 0.0f;
        float w2r = v2 ? g_roww[rr2] : 0.0f;
        float* y1 = y + (size_t)t1 * H_DIM;
        float* y2 = y + (size_t)t2 * H_DIM;
#pragma unroll
        for (int ni = 0; ni < 4; ni++) {
            int col = n0 + wn * 32 + ni * 8 + c2;
            if (v1) {
                atomicAdd(y1 + col,     acc[mi][ni][0] * w1r);
                atomicAdd(y1 + col + 1, acc[mi][ni][1] * w1r);
            }
            if (v2) {
                atomicAdd(y2 + col,     acc[mi][ni][2] * w2r);
                atomicAdd(y2 + col + 1, acc[mi][ni][3] * w2r);
            }
        }
    }
}

// ---------------- launch ----------------
extern "C" void kernel_launch(void* const* d_in, const int* in_sizes, int n_in,
                              void* d_out, int out_size) {
    const float* x  = (const float*)d_in[0];   // [B,S,H]
    const float* rw = (const float*)d_in[1];   // [E,H]
    const float* w1 = (const float*)d_in[2];   // [E,H,I]
    const float* w2 = (const float*)d_in[3];   // [E,I,H]
    float* y = (float*)d_out;

    cudaMemsetAsync(d_out, 0, (size_t)T_TOK * H_DIM * sizeof(float));

    init_kernel<<<(TKB + 255) / 256, 256>>>();
    router_kernel<<<T_TOK / 8, 256>>>(x, rw);
    int write_tpe = (out_size >= T_TOK * H_DIM + N_EXP) ? 1 : 0;
    scan_kernel<<<1, 1>>>(y + (size_t)T_TOK * H_DIM, write_tpe);
    scatter_kernel<<<TK / 256, 256>>>();

    dim3 g1(I_DIM / 128, (TK + 127) / 128, N_EXP);
    gemm1_mma<<<g1, 256>>>(x, w1);

    dim3 g2(H_DIM / 128, (TK + 127) / 128, N_EXP);
    gemm2_mma<<<g2, 256>>>(w2, y);
}

// round 10
// speedup vs baseline: 3.1072x; 1.1334x over previous
#include <cuda_runtime.h>
#include <cuda_bf16.h>
#include <math.h>
#include <stdint.h>

// Problem constants: B=4, S=2048, H=2048, I=4096, E=8, K=2
#define T_TOK 8192
#define H_DIM 2048
#define I_DIM 4096
#define N_EXP 8
#define K_TOP 2
#define TK (T_TOK * K_TOP)
#define TKB (TK + 256)   // pad for +127 tile overread

// ---------------- device scratch (256MB total — same as passing R7) ----------
__device__ int   g_counts[N_EXP];
__device__ int   g_seg[N_EXP + 1];
__device__ int   g_cursor[N_EXP];
__device__ int   g_expidx[TK];
__device__ float g_expw[TK];
__device__ int   g_rowtok[TKB];
__device__ float g_roww[TKB];
__device__ __nv_bfloat16 g_h_hi[(size_t)TK * I_DIM];  // 128MB
__device__ __nv_bfloat16 g_h_lo[(size_t)TK * I_DIM];  // 128MB

// ---------------- helpers ----------------
__device__ __forceinline__ float gelu_tanh(float v) {
    const float c = 0.7978845608028654f;
    float u = c * (v + 0.044715f * v * v * v);
    return 0.5f * v * (1.0f + tanhf(u));
}
__device__ __forceinline__ uint32_t smem_u32(const void* p) {
    uint32_t a;
    asm("{ .reg .u64 t; cvta.to.shared.u64 t, %1; cvt.u32.u64 %0, t; }" : "=r"(a) : "l"(p));
    return a;
}
__device__ __forceinline__ void mma16816(float* c, uint32_t a0, uint32_t a1,
                                         uint32_t a2, uint32_t a3,
                                         uint32_t b0, uint32_t b1) {
    asm volatile(
        "mma.sync.aligned.m16n8k16.row.col.f32.bf16.bf16.f32 "
        "{%0,%1,%2,%3}, {%4,%5,%6,%7}, {%8,%9}, {%0,%1,%2,%3};"
        : "+f"(c[0]), "+f"(c[1]), "+f"(c[2]), "+f"(c[3])
        : "r"(a0), "r"(a1), "r"(a2), "r"(a3), "r"(b0), "r"(b1));
}
__device__ __forceinline__ void ldsm_x4(uint32_t* d, uint32_t addr) {
    asm volatile("ldmatrix.sync.aligned.m8n8.x4.shared.b16 {%0,%1,%2,%3}, [%4];"
        : "=r"(d[0]), "=r"(d[1]), "=r"(d[2]), "=r"(d[3]) : "r"(addr));
}
__device__ __forceinline__ void ldsm_x4_t(uint32_t* d, uint32_t addr) {
    asm volatile("ldmatrix.sync.aligned.m8n8.x4.trans.shared.b16 {%0,%1,%2,%3}, [%4];"
        : "=r"(d[0]), "=r"(d[1]), "=r"(d[2]), "=r"(d[3]) : "r"(addr));
}
// split two fp32 (f.x = element k, f.y = element k+1) into hi/lo bf16x2 regs.
__device__ __forceinline__ void cvt_pair(float2 f, uint32_t& hi, uint32_t& lo) {
    asm("cvt.rn.bf16x2.f32 %0, %1, %2;" : "=r"(hi) : "f"(f.y), "f"(f.x));
    float f0h = __uint_as_float(hi << 16);
    float f1h = __uint_as_float(hi & 0xffff0000u);
    float r0 = f.x - f0h;
    float r1 = f.y - f1h;
    asm("cvt.rn.bf16x2.f32 %0, %1, %2;" : "=r"(lo) : "f"(r1), "f"(r0));
}

// ---------------- small kernels (verbatim from passing R7) ----------------
__global__ void init_kernel() {
    int i = blockIdx.x * blockDim.x + threadIdx.x;
    if (i < TKB) { g_rowtok[i] = 0; g_roww[i] = 0.0f; }
    if (i < N_EXP) g_counts[i] = 0;
}

__global__ void router_kernel(const float* __restrict__ x,
                              const float* __restrict__ rw) {
    int warp = (blockIdx.x * blockDim.x + threadIdx.x) >> 5;
    int lane = threadIdx.x & 31;
    if (warp >= T_TOK) return;
    const float* xr = x + (size_t)warp * H_DIM;
    float acc[N_EXP];
#pragma unroll
    for (int e = 0; e < N_EXP; e++) acc[e] = 0.0f;
    for (int h = lane; h < H_DIM; h += 32) {
        float xv = xr[h];
#pragma unroll
        for (int e = 0; e < N_EXP; e++)
            acc[e] = fmaf(xv, rw[e * H_DIM + h], acc[e]);
    }
#pragma unroll
    for (int off = 16; off > 0; off >>= 1)
#pragma unroll
        for (int e = 0; e < N_EXP; e++)
            acc[e] += __shfl_xor_sync(0xffffffffu, acc[e], off);
    if (lane == 0) {
        float mx = acc[0];
#pragma unroll
        for (int e = 1; e < N_EXP; e++) mx = fmaxf(mx, acc[e]);
        float p[N_EXP]; float s = 0.0f;
#pragma unroll
        for (int e = 0; e < N_EXP; e++) { p[e] = expf(acc[e] - mx); s += p[e]; }
        float inv = 1.0f / s;
        int e0 = 0;
#pragma unroll
        for (int e = 1; e < N_EXP; e++) if (p[e] > p[e0]) e0 = e;
        int e1 = (e0 == 0) ? 1 : 0;
#pragma unroll
        for (int e = 0; e < N_EXP; e++) if (e != e0 && p[e] > p[e1]) e1 = e;
        g_expidx[2 * warp + 0] = e0; g_expw[2 * warp + 0] = p[e0] * inv;
        g_expidx[2 * warp + 1] = e1; g_expw[2 * warp + 1] = p[e1] * inv;
        atomicAdd(&g_counts[e0], 1);
        atomicAdd(&g_counts[e1], 1);
    }
}

__global__ void scan_kernel(float* tpe_out, int write_tpe) {
    if (blockIdx.x == 0 && threadIdx.x == 0) {
        int s = 0;
        for (int e = 0; e < N_EXP; e++) {
            g_seg[e] = s;
            g_cursor[e] = s;
            int c = g_counts[e];
            if (write_tpe) tpe_out[e] = (float)c;
            s += c;
        }
        g_seg[N_EXP] = s;
    }
}

__global__ void scatter_kernel() {
    int i = blockIdx.x * blockDim.x + threadIdx.x;
    if (i >= TK) return;
    int e = g_expidx[i];
    int p = atomicAdd(&g_cursor[e], 1);
    g_rowtok[p] = i >> 1;
    g_roww[p]   = g_expw[i];
}

// ---------------- mma.sync grouped GEMMs -----------------------------------
// CTA 128x128x16, 8 warps (2M x 4N), warp tile 64x32.
// A: bf16 hi/lo smem (pitch 12 words = 48B) -> ldmatrix.x4, conflict-free.
// B: fp32 streamed from d_in, converted to bf16 hi/lo AT SMEM-STORE TIME
//    (pitch 68 words = 272B) -> ldmatrix.x4.trans, conflict-free.
#define PAW 12
#define PBW 68
#define A_STAGE_B (128 * PAW * 4)
#define B_STAGE_B (16 * PBW * 4)

__global__ __launch_bounds__(256, 2)
void gemm1_mma(const float* __restrict__ x, const float* __restrict__ w1) {
    __shared__ __align__(16) uint32_t AsH[2][128 * PAW];
    __shared__ __align__(16) uint32_t AsL[2][128 * PAW];
    __shared__ __align__(16) uint32_t BsH[2][16 * PBW];
    __shared__ __align__(16) uint32_t BsL[2][16 * PBW];

    int e = blockIdx.z;
    int seg0 = g_seg[e], seg1 = g_seg[e + 1];
    int row0 = seg0 + blockIdx.y * 128;
    if (row0 >= seg1) return;
    int n0 = blockIdx.x * 128;

    const float* Bp = w1 + (size_t)e * H_DIM * I_DIM;   // [H][I]

    int tid = threadIdx.x;
    int wid = tid >> 5, l = tid & 31;
    int wm = wid >> 2, wn = wid & 3;
    int r7 = l >> 2, c2 = (l & 3) * 2;

    // A loader: 512 float4 (128 rows x 4 quads), 2 per thread (gathered rows)
    int ia0 = tid, ia1 = tid + 256;
    int ar0 = ia0 >> 2, aq0 = ia0 & 3;
    int ar1 = ia1 >> 2, aq1 = ia1 & 3;
    int tok0 = min(g_rowtok[row0 + ar0], T_TOK - 1);
    int tok1 = min(g_rowtok[row0 + ar1], T_TOK - 1);
    const float4* asrc0 = (const float4*)(x + (size_t)tok0 * H_DIM) + aq0;
    const float4* asrc1 = (const float4*)(x + (size_t)tok1 * H_DIM) + aq1;
    // B loader: 512 float4 (16 rows x 32 quads), 2 per thread (fp32 weights)
    int br0 = ia0 >> 5, bq0 = ia0 & 31;
    int br1 = ia1 >> 5, bq1 = ia1 & 31;
    const float4* bsrc0 = (const float4*)(Bp + (size_t)br0 * I_DIM + n0) + bq0;
    const float4* bsrc1 = (const float4*)(Bp + (size_t)br1 * I_DIM + n0) + bq1;
    const size_t bstep = (size_t)4 * I_DIM;   // 16 rows in float4 units

    // fragment smem addresses (ldmatrix)
    uint32_t uAsH = smem_u32(AsH), uAsL = smem_u32(AsL);
    uint32_t uBsH = smem_u32(BsH), uBsL = smem_u32(BsL);
    uint32_t aoff[4];
#pragma unroll
    for (int mi = 0; mi < 4; mi++)
        aoff[mi] = (uint32_t)((wm * 64 + mi * 16 + (l & 15)) * (PAW * 4) + (l >> 4) * 16);
    uint32_t boff[2];
#pragma unroll
    for (int pi = 0; pi < 2; pi++)
        boff[pi] = (uint32_t)((l & 15) * (PBW * 4) + (wn * 32 + pi * 16 + (l >> 4) * 8) * 2);

    float acc[4][4][4];
#pragma unroll
    for (int mi = 0; mi < 4; mi++)
#pragma unroll
        for (int ni = 0; ni < 4; ni++)
#pragma unroll
            for (int q = 0; q < 4; q++) acc[mi][ni][q] = 0.0f;

    const int NC = H_DIM / 16;   // 128
    float4 av0 = asrc0[0], av1 = asrc1[0];
    float4 bv0 = bsrc0[0], bv1 = bsrc1[0];

    for (int c = 0; c < NC; c++) {
        int s = c & 1;
        {   // A store (cvt at store time)
            uint32_t h0, l0, h1, l1;
            cvt_pair(make_float2(av0.x, av0.y), h0, l0);
            cvt_pair(make_float2(av0.z, av0.w), h1, l1);
            *(uint2*)&AsH[s][ar0 * PAW + aq0 * 2] = make_uint2(h0, h1);
            *(uint2*)&AsL[s][ar0 * PAW + aq0 * 2] = make_uint2(l0, l1);
            cvt_pair(make_float2(av1.x, av1.y), h0, l0);
            cvt_pair(make_float2(av1.z, av1.w), h1, l1);
            *(uint2*)&AsH[s][ar1 * PAW + aq1 * 2] = make_uint2(h0, h1);
            *(uint2*)&AsL[s][ar1 * PAW + aq1 * 2] = make_uint2(l0, l1);
        }
        {   // B store (cvt at store time)
            uint32_t h0, l0, h1, l1;
            cvt_pair(make_float2(bv0.x, bv0.y), h0, l0);
            cvt_pair(make_float2(bv0.z, bv0.w), h1, l1);
            *(uint2*)&BsH[s][br0 * PBW + bq0 * 2] = make_uint2(h0, h1);
            *(uint2*)&BsL[s][br0 * PBW + bq0 * 2] = make_uint2(l0, l1);
            cvt_pair(make_float2(bv1.x, bv1.y), h0, l0);
            cvt_pair(make_float2(bv1.z, bv1.w), h1, l1);
            *(uint2*)&BsH[s][br1 * PBW + bq1 * 2] = make_uint2(h0, h1);
            *(uint2*)&BsL[s][br1 * PBW + bq1 * 2] = make_uint2(l0, l1);
        }
        if (c + 1 < NC) {
            int k4 = (c + 1) * 4;   // 16 floats = 4 float4
            av0 = asrc0[k4];
            av1 = asrc1[k4];
            bv0 = bsrc0[(size_t)(c + 1) * bstep];
            bv1 = bsrc1[(size_t)(c + 1) * bstep];
        }
        __syncthreads();

        uint32_t sA = (uint32_t)s * A_STAGE_B;
        uint32_t sB = (uint32_t)s * B_STAGE_B;
        uint32_t aH[4][4], aL[4][4];
#pragma unroll
        for (int mi = 0; mi < 4; mi++) {
            ldsm_x4(aH[mi], uAsH + sA + aoff[mi]);
            ldsm_x4(aL[mi], uAsL + sA + aoff[mi]);
        }
        uint32_t bH[4][2], bL[4][2];
#pragma unroll
        for (int pi = 0; pi < 2; pi++) {
            uint32_t d[4];
            ldsm_x4_t(d, uBsH + sB + boff[pi]);
            bH[2 * pi][0] = d[0]; bH[2 * pi][1] = d[1];
            bH[2 * pi + 1][0] = d[2]; bH[2 * pi + 1][1] = d[3];
            ldsm_x4_t(d, uBsL + sB + boff[pi]);
            bL[2 * pi][0] = d[0]; bL[2 * pi][1] = d[1];
            bL[2 * pi + 1][0] = d[2]; bL[2 * pi + 1][1] = d[3];
        }
#pragma unroll
        for (int ni = 0; ni < 4; ni++)
#pragma unroll
            for (int mi = 0; mi < 4; mi++) {
                mma16816(acc[mi][ni], aH[mi][0], aH[mi][1], aH[mi][2], aH[mi][3],
                         bH[ni][0], bH[ni][1]);
                mma16816(acc[mi][ni], aH[mi][0], aH[mi][1], aH[mi][2], aH[mi][3],
                         bL[ni][0], bL[ni][1]);
                mma16816(acc[mi][ni], aL[mi][0], aL[mi][1], aL[mi][2], aL[mi][3],
                         bH[ni][0], bH[ni][1]);
            }
    }

    // epilogue: GELU -> split -> g_h_hi / g_h_lo (valid rows only)
#pragma unroll
    for (int mi = 0; mi < 4; mi++) {
        int r1 = row0 + wm * 64 + mi * 16 + r7;
        int r2 = r1 + 8;
#pragma unroll
        for (int ni = 0; ni < 4; ni++) {
            int col = n0 + wn * 32 + ni * 8 + c2;
            if (r1 < seg1) {
                float2 v = make_float2(gelu_tanh(acc[mi][ni][0]), gelu_tanh(acc[mi][ni][1]));
                uint32_t hw, lw;
                cvt_pair(v, hw, lw);
                size_t o = (size_t)r1 * I_DIM + col;
                *(uint32_t*)&g_h_hi[o] = hw;
                *(uint32_t*)&g_h_lo[o] = lw;
            }
            if (r2 < seg1) {
                float2 v = make_float2(gelu_tanh(acc[mi][ni][2]), gelu_tanh(acc[mi][ni][3]));
                uint32_t hw, lw;
                cvt_pair(v, hw, lw);
                size_t o = (size_t)r2 * I_DIM + col;
                *(uint32_t*)&g_h_hi[o] = hw;
                *(uint32_t*)&g_h_lo[o] = lw;
            }
        }
    }
}

__global__ __launch_bounds__(256, 2)
void gemm2_mma(const float* __restrict__ w2, float* __restrict__ y) {
    __shared__ __align__(16) uint32_t AsH[2][128 * PAW];
    __shared__ __align__(16) uint32_t AsL[2][128 * PAW];
    __shared__ __align__(16) uint32_t BsH[2][16 * PBW];
    __shared__ __align__(16) uint32_t BsL[2][16 * PBW];

    int e = blockIdx.z;
    int seg0 = g_seg[e], seg1 = g_seg[e + 1];
    int row0 = seg0 + blockIdx.y * 128;
    if (row0 >= seg1) return;
    int n0 = blockIdx.x * 128;

    const float* Bp = w2 + (size_t)e * I_DIM * H_DIM;   // [I][H]

    int tid = threadIdx.x;
    int wid = tid >> 5, l = tid & 31;
    int wm = wid >> 2, wn = wid & 3;
    int r7 = l >> 2, c2 = (l & 3) * 2;

    // A loader: pre-split bf16 g_h, 128 rows x 2 halves, clamp row (masked later)
    int arow = tid >> 1, ahalf = tid & 1;
    int arid = min(row0 + arow, TK - 1);
    const uint4* ahsrc = (const uint4*)(g_h_hi + (size_t)arid * I_DIM) + ahalf;
    const uint4* alsrc = (const uint4*)(g_h_lo + (size_t)arid * I_DIM) + ahalf;
    // B loader: 512 float4 (16 rows x 32 quads), fp32 weights
    int ia0 = tid, ia1 = tid + 256;
    int br0 = ia0 >> 5, bq0 = ia0 & 31;
    int br1 = ia1 >> 5, bq1 = ia1 & 31;
    const float4* bsrc0 = (const float4*)(Bp + (size_t)br0 * H_DIM + n0) + bq0;
    const float4* bsrc1 = (const float4*)(Bp + (size_t)br1 * H_DIM + n0) + bq1;
    const size_t bstep = (size_t)4 * H_DIM;

    uint32_t uAsH = smem_u32(AsH), uAsL = smem_u32(AsL);
    uint32_t uBsH = smem_u32(BsH), uBsL = smem_u32(BsL);
    uint32_t aoff[4];
#pragma unroll
    for (int mi = 0; mi < 4; mi++)
        aoff[mi] = (uint32_t)((wm * 64 + mi * 16 + (l & 15)) * (PAW * 4) + (l >> 4) * 16);
    uint32_t boff[2];
#pragma unroll
    for (int pi = 0; pi < 2; pi++)
        boff[pi] = (uint32_t)((l & 15) * (PBW * 4) + (wn * 32 + pi * 16 + (l >> 4) * 8) * 2);

    float acc[4][4][4];
#pragma unroll
    for (int mi = 0; mi < 4; mi++)
#pragma unroll
        for (int ni = 0; ni < 4; ni++)
#pragma unroll
            for (int q = 0; q < 4; q++) acc[mi][ni][q] = 0.0f;

    const int NC = I_DIM / 16;   // 256
    uint4 avh = ahsrc[0], avl = alsrc[0];
    float4 bv0 = bsrc0[0], bv1 = bsrc1[0];

    for (int c = 0; c < NC; c++) {
        int s = c & 1;
        *(uint4*)&AsH[s][arow * PAW + ahalf * 4] = avh;
        *(uint4*)&AsL[s][arow * PAW + ahalf * 4] = avl;
        {   // B store (cvt at store time)
            uint32_t h0, l0, h1, l1;
            cvt_pair(make_float2(bv0.x, bv0.y), h0, l0);
            cvt_pair(make_float2(bv0.z, bv0.w), h1, l1);
            *(uint2*)&BsH[s][br0 * PBW + bq0 * 2] = make_uint2(h0, h1);
            *(uint2*)&BsL[s][br0 * PBW + bq0 * 2] = make_uint2(l0, l1);
            cvt_pair(make_float2(bv1.x, bv1.y), h0, l0);
            cvt_pair(make_float2(bv1.z, bv1.w), h1, l1);
            *(uint2*)&BsH[s][br1 * PBW + bq1 * 2] = make_uint2(h0, h1);
            *(uint2*)&BsL[s][br1 * PBW + bq1 * 2] = make_uint2(l0, l1);
        }
        if (c + 1 < NC) {
            int k2 = (c + 1) * 2;   // 16 bf16 = 2 uint4
            avh = ahsrc[k2];
            avl = alsrc[k2];
            bv0 = bsrc0[(size_t)(c + 1) * bstep];
            bv1 = bsrc1[(size_t)(c + 1) * bstep];
        }
        __syncthreads();

        uint32_t sA = (uint32_t)s * A_STAGE_B;
        uint32_t sB = (uint32_t)s * B_STAGE_B;
        uint32_t aH[4][4], aL[4][4];
#pragma unroll
        for (int mi = 0; mi < 4; mi++) {
            ldsm_x4(aH[mi], uAsH + sA + aoff[mi]);
            ldsm_x4(aL[mi], uAsL + sA + aoff[mi]);
        }
        uint32_t bH[4][2], bL[4][2];
#pragma unroll
        for (int pi = 0; pi < 2; pi++) {
            uint32_t d[4];
            ldsm_x4_t(d, uBsH + sB + boff[pi]);
            bH[2 * pi][0] = d[0]; bH[2 * pi][1] = d[1];
            bH[2 * pi + 1][0] = d[2]; bH[2 * pi + 1][1] = d[3];
            ldsm_x4_t(d, uBsL + sB + boff[pi]);
            bL[2 * pi][0] = d[0]; bL[2 * pi][1] = d[1];
            bL[2 * pi + 1][0] = d[2]; bL[2 * pi + 1][1] = d[3];
        }
#pragma unroll
        for (int ni = 0; ni < 4; ni++)
#pragma unroll
            for (int mi = 0; mi < 4; mi++) {
                mma16816(acc[mi][ni], aH[mi][0], aH[mi][1], aH[mi][2], aH[mi][3],
                         bH[ni][0], bH[ni][1]);
                mma16816(acc[mi][ni], aH[mi][0], aH[mi][1], aH[mi][2], aH[mi][3],
                         bL[ni][0], bL[ni][1]);
                mma16816(acc[mi][ni], aL[mi][0], aL[mi][1], aL[mi][2], aL[mi][3],
                         bH[ni][0], bH[ni][1]);
            }
    }

    // epilogue: weighted scatter-add into y (invalid rows masked)
#pragma unroll
    for (int mi = 0; mi < 4; mi++) {
        int rr1 = row0 + wm * 64 + mi * 16 + r7;
        int rr2 = rr1 + 8;
        bool v1 = rr1 < seg1, v2 = rr2 < seg1;
        int t1 = v1 ? g_rowtok[rr1] : 0;
        int t2 = v2 ? g_rowtok[rr2] : 0;
        float w1r = v1 ? g_roww[rr1] : 0.0f;
        float w2r = v2 ? g_roww[rr2] : 0.0f;
        float* y1 = y + (size_t)t1 * H_DIM;
        float* y2 = y + (size_t)t2 * H_DIM;
#pragma unroll
        for (int ni = 0; ni < 4; ni++) {
            int col = n0 + wn * 32 + ni * 8 + c2;
            if (v1) {
                atomicAdd(y1 + col,     acc[mi][ni][0] * w1r);
                atomicAdd(y1 + col + 1, acc[mi][ni][1] * w1r);
            }
            if (v2) {
                atomicAdd(y2 + col,     acc[mi][ni][2] * w2r);
                atomicAdd(y2 + col + 1, acc[mi][ni][3] * w2r);
            }
        }
    }
}

// ---------------- launch ----------------
extern "C" void kernel_launch(void* const* d_in, const int* in_sizes, int n_in,
                              void* d_out, int out_size) {
    const float* x  = (const float*)d_in[0];   // [B,S,H]
    const float* rw = (const float*)d_in[1];   // [E,H]
    const float* w1 = (const float*)d_in[2];   // [E,H,I]
    const float* w2 = (const float*)d_in[3];   // [E,I,H]
    float* y = (float*)d_out;

    cudaMemsetAsync(d_out, 0, (size_t)T_TOK * H_DIM * sizeof(float));

    init_kernel<<<(TKB + 255) / 256, 256>>>();
    router_kernel<<<T_TOK / 8, 256>>>(x, rw);
    int write_tpe = (out_size >= T_TOK * H_DIM + N_EXP) ? 1 : 0;
    scan_kernel<<<1, 1>>>(y + (size_t)T_TOK * H_DIM, write_tpe);
    scatter_kernel<<<TK / 256, 256>>>();

    dim3 g1(I_DIM / 128, (TK + 127) / 128, N_EXP);
    gemm1_mma<<<g1, 256>>>(x, w1);

    dim3 g2(H_DIM / 128, (TK + 127) / 128, N_EXP);
    gemm2_mma<<<g2, 256>>>(w2, y);
}